// round 16
// baseline (speedup 1.0000x reference)
#include <cuda_runtime.h>
#include <math.h>

#define NTRAIN 10000
#define SEQL   192
#define PREDL  96
#define CHN    8
#define FDIM   1536     // SEQL*CHN
#define YROW   768      // PREDL*CHN
#define TOPM   20
#define BSZ    32
#define NP     3
#define WIN_HALF 287    // (2*(SEQ+PRED)-1 - 1)/2

#define STREAM cudaStreamPerThread

// ---------------- tiny device globals (~16 KB; lazy module load stays in-pool) ----
__device__ int   g_topidx[NP * BSZ * TOPM];
__device__ float g_spart[NP * BSZ * TOPM];
__device__ float g_M[64];
__device__ float g_wqbk[8];
__device__ float g_wkbq[8];
__device__ float g_bqbk[1];

// ---------------- fast exp (FMA-only, scalar-only) ----------------
__device__ __forceinline__ float fast_exp(float x) {
    x = fmaxf(x, -87.0f);
    float t = x * 1.4426950408889634f;
    float z = t + 12582912.0f;
    float n = z - 12582912.0f;
    float f = t - n;
    float p = 0.0013333558146428443f;
    p = fmaf(p, f, 0.009618129107628477f);
    p = fmaf(p, f, 0.05550410866482158f);
    p = fmaf(p, f, 0.2402265069591007f);
    p = fmaf(p, f, 0.6931471805599453f);
    p = fmaf(p, f, 1.0f);
    int ei = (int)n;
    return p * __int_as_float((ei + 127) << 23);
}

__global__ void prefill_kernel(float* __restrict__ out) {
    int i = blockIdx.x * blockDim.x + threadIdx.x;
    if (i < NP * BSZ * YROW) out[i] = 2.0f;
}
__global__ void clear_scratch_kernel(float* __restrict__ scr) {
    int i = blockIdx.x * blockDim.x + threadIdx.x;
    if (i < NP * NTRAIN) scr[i] = 0.0f;
}

// ---------------- prep: M = Wq Wk^T (8x8), Wq.bk, Wk.bq, bq.bk ----------------
__global__ void prep_kernel(const float* __restrict__ Wq, const float* __restrict__ bq,
                            const float* __restrict__ Wk, const float* __restrict__ bk) {
    int t = threadIdx.x;
    if (t < 64) {
        int c = t >> 3, d = t & 7;
        float s = 0.f;
        for (int e = 0; e < 512; e++) s = fmaf(Wq[c * 512 + e], Wk[d * 512 + e], s);
        g_M[t] = s;
    } else if (t < 72) {
        int c = t - 64;
        float s = 0.f;
        for (int e = 0; e < 512; e++) s = fmaf(Wq[c * 512 + e], bk[e], s);
        g_wqbk[c] = s;
    } else if (t < 80) {
        int c = t - 72;
        float s = 0.f;
        for (int e = 0; e < 512; e++) s = fmaf(Wk[c * 512 + e], bq[e], s);
        g_wkbq[c] = s;
    } else if (t == 80) {
        float s = 0.f;
        for (int e = 0; e < 512; e++) s = fmaf(bq[e], bk[e], s);
        g_bqbk[0] = s;
    }
}

// ---------------- grouped-K GEMM, conflict-free B fragments (R14-proven config) ----
__global__ __launch_bounds__(256) void gemm_norm_kernel(const float* __restrict__ train,
                                                        const float* __restrict__ W,
                                                        const float* __restrict__ bsim,
                                                        float* __restrict__ scr) {
    int p = blockIdx.z;
    int g = 4 >> p;                      // 4, 2, 1
    int Keff = FDIM / g;                 // 384, 768, 1536
    float invg = 1.0f / (float)g;
    __shared__ float As[16][132];
    __shared__ float Bs[16][128];
    __shared__ float lastm[128][8];
    __shared__ float red[16][16][8];
    int tid = threadIdx.x;
    int tx = tid & 15, ty = tid >> 4;
    int row0 = blockIdx.x * 128, col0 = blockIdx.y * 128;

    if (tid < 128) {
        int n = row0 + tid;
        float4 s0 = make_float4(0.f, 0.f, 0.f, 0.f);
        float4 s1 = make_float4(0.f, 0.f, 0.f, 0.f);
        if (n < NTRAIN) {
            const float* rp = train + (long)n * FDIM + (SEQL - g) * CHN;
            for (int j = 0; j < g; j++) {
                float4 a = *(const float4*)&rp[j * CHN + 0];
                float4 b = *(const float4*)&rp[j * CHN + 4];
                s0.x += a.x; s0.y += a.y; s0.z += a.z; s0.w += a.w;
                s1.x += b.x; s1.y += b.y; s1.z += b.z; s1.w += b.w;
            }
        }
        lastm[tid][0] = s0.x * invg; lastm[tid][1] = s0.y * invg;
        lastm[tid][2] = s0.z * invg; lastm[tid][3] = s0.w * invg;
        lastm[tid][4] = s1.x * invg; lastm[tid][5] = s1.y * invg;
        lastm[tid][6] = s1.z * invg; lastm[tid][7] = s1.w * invg;
    }
    __syncthreads();

    float acc[8][8];
#pragma unroll
    for (int i = 0; i < 8; i++)
#pragma unroll
        for (int j = 0; j < 8; j++) acc[i][j] = 0.f;

    int lbr = tid >> 5;
    int lbc = (tid & 31) * 4;
    int ar = tid >> 1;
    int ahalf = tid & 1;

    for (int k0 = 0; k0 < Keff; k0 += 16) {
        {
            int n = row0 + ar;
            int gi = (k0 >> 3) + ahalf;
            float4 s0 = make_float4(0.f, 0.f, 0.f, 0.f);
            float4 s1 = make_float4(0.f, 0.f, 0.f, 0.f);
            if (n < NTRAIN) {
                const float* rp = train + (long)n * FDIM + (gi * g) * CHN;
                for (int j = 0; j < g; j++) {
                    float4 a = *(const float4*)&rp[j * CHN + 0];
                    float4 b = *(const float4*)&rp[j * CHN + 4];
                    s0.x += a.x; s0.y += a.y; s0.z += a.z; s0.w += a.w;
                    s1.x += b.x; s1.y += b.y; s1.z += b.z; s1.w += b.w;
                }
            }
            int kk = ahalf * 8;
            As[kk + 0][ar] = s0.x * invg - lastm[ar][0];
            As[kk + 1][ar] = s0.y * invg - lastm[ar][1];
            As[kk + 2][ar] = s0.z * invg - lastm[ar][2];
            As[kk + 3][ar] = s0.w * invg - lastm[ar][3];
            As[kk + 4][ar] = s1.x * invg - lastm[ar][4];
            As[kk + 5][ar] = s1.y * invg - lastm[ar][5];
            As[kk + 6][ar] = s1.z * invg - lastm[ar][6];
            As[kk + 7][ar] = s1.w * invg - lastm[ar][7];
        }
#pragma unroll
        for (int h = 0; h < 2; h++) {
            int r = lbr + h * 8;
            int kp = k0 + r;
            int gi = kp >> 3, c = kp & 7;
            const float* wbase = W + ((long)(gi * g * 8 + c)) * FDIM + col0 + lbc;
            float4 s = make_float4(0.f, 0.f, 0.f, 0.f);
            for (int jj = 0; jj < g; jj++) {
                float4 v = *(const float4*)(wbase + (long)jj * 8 * FDIM);
                s.x += v.x; s.y += v.y; s.z += v.z; s.w += v.w;
            }
            *(float4*)&Bs[r][lbc] = s;
        }
        __syncthreads();
#pragma unroll
        for (int kk = 0; kk < 16; kk++) {
            float a[8], b[8];
#pragma unroll
            for (int i = 0; i < 8; i++) a[i] = As[kk][ty * 8 + i];
            float4 bv0 = *(const float4*)&Bs[kk][tx * 4];
            float4 bv1 = *(const float4*)&Bs[kk][64 + tx * 4];
            b[0] = bv0.x; b[1] = bv0.y; b[2] = bv0.z; b[3] = bv0.w;
            b[4] = bv1.x; b[5] = bv1.y; b[6] = bv1.z; b[7] = bv1.w;
#pragma unroll
            for (int i = 0; i < 8; i++)
#pragma unroll
                for (int j = 0; j < 8; j++) acc[i][j] = fmaf(a[i], b[j], acc[i][j]);
        }
        __syncthreads();
    }
    float bb[8];
#pragma unroll
    for (int j = 0; j < 4; j++) bb[j] = bsim[col0 + tx * 4 + j];
#pragma unroll
    for (int j = 0; j < 4; j++) bb[4 + j] = bsim[col0 + 64 + tx * 4 + j];
#pragma unroll
    for (int i = 0; i < 8; i++) {
        float s = 0.f;
#pragma unroll
        for (int j = 0; j < 8; j++) { float v = acc[i][j] + bb[j]; s = fmaf(v, v, s); }
        red[ty][tx][i] = s;
    }
    __syncthreads();
    if (tx < 8) {
        float s = 0.f;
#pragma unroll
        for (int q = 0; q < 16; q++) s += red[ty][q][tx];
        int grow = row0 + ty * 8 + tx;
        if (grow < NTRAIN) atomicAdd(&scr[p * NTRAIN + grow], s);
    }
}

// ---------------- fused bx/u/sims/top-20 per (p,b) (float4 u + register-u sims) ----
__global__ __launch_bounds__(256) void topk_fused_kernel(const float* __restrict__ x,
                                                         const int* __restrict__ index,
                                                         const float* __restrict__ train,
                                                         const float* __restrict__ W,
                                                         const float* __restrict__ bsim,
                                                         const float* __restrict__ scr) {
    __shared__ float sv[NTRAIN];
    __shared__ float u[FDIM];
    __shared__ float lastx[8];
    __shared__ float Usum[8];
    __shared__ float wredf[8];
    __shared__ int   wredi[8];
    __shared__ float s_bxn, s_cdot;
    int tid = threadIdx.x;
    int lane = tid & 31, wid = tid >> 5;
    int pb = blockIdx.x;
    int p = pb >> 5, b = pb & 31;
    int g = 4 >> p;
    float invg = 1.0f / (float)g;
    const float* xr = x + (long)b * FDIM;
    float* xp = sv + 2048;
    float* bx = sv;

    if (tid < 8) {
        float s = 0.f;
        for (int j = 0; j < g; j++) s += xr[(SEQL - g + j) * CHN + tid];
        lastx[tid] = s * invg;
    }
    __syncthreads();
    for (int f = tid; f < FDIM; f += 256) {
        int l = f >> 3, c = f & 7;
        int B = (l / g) * g;
        float s = 0.f;
        for (int j = 0; j < g; j++) s += xr[(B + j) * CHN + c];
        xp[f] = s * invg - lastx[c];
    }
    __syncthreads();
    float a0 = bsim[tid], a1 = bsim[tid + 256], a2 = bsim[tid + 512];
    float a3 = bsim[tid + 768], a4 = bsim[tid + 1024], a5 = bsim[tid + 1280];
    for (int f = 0; f < FDIM; f++) {
        float xv = xp[f];
        const float* wr = W + (long)f * FDIM + tid;
        a0 = fmaf(xv, wr[0], a0);    a1 = fmaf(xv, wr[256], a1);
        a2 = fmaf(xv, wr[512], a2);  a3 = fmaf(xv, wr[768], a3);
        a4 = fmaf(xv, wr[1024], a4); a5 = fmaf(xv, wr[1280], a5);
    }
    __syncthreads();
    bx[tid] = a0; bx[tid + 256] = a1; bx[tid + 512] = a2;
    bx[tid + 768] = a3; bx[tid + 1024] = a4; bx[tid + 1280] = a5;
    float sq = a0 * a0 + a1 * a1 + a2 * a2 + a3 * a3 + a4 * a4 + a5 * a5;
    float cd = a0 * bsim[tid] + a1 * bsim[tid + 256] + a2 * bsim[tid + 512]
             + a3 * bsim[tid + 768] + a4 * bsim[tid + 1024] + a5 * bsim[tid + 1280];
#pragma unroll
    for (int o = 16; o; o >>= 1) {
        sq += __shfl_xor_sync(0xffffffffu, sq, o);
        cd += __shfl_xor_sync(0xffffffffu, cd, o);
    }
    if (lane == 0) { wredf[wid] = sq; wredi[wid] = __float_as_int(cd); }
    __syncthreads();
    if (tid == 0) {
        float t1 = 0.f, t2 = 0.f;
        for (int w = 0; w < 8; w++) { t1 += wredf[w]; t2 += __int_as_float(wredi[w]); }
        s_bxn = fmaxf(sqrtf(fmaxf(t1, 0.f)), 1e-12f);
        s_cdot = t2;
    }
    __syncthreads();
    // u[i] = W[i,:] . bx — warp per row, float4
    for (int i = wid; i < FDIM; i += 8) {
        const float* wr = W + (long)i * FDIM;
        float s = 0.f;
#pragma unroll
        for (int k = 0; k < 12; k++) {
            float4 wv = *(const float4*)&wr[k * 128 + lane * 4];
            float4 xv = *(const float4*)&bx[k * 128 + lane * 4];
            s = fmaf(wv.x, xv.x, s); s = fmaf(wv.y, xv.y, s);
            s = fmaf(wv.z, xv.z, s); s = fmaf(wv.w, xv.w, s);
        }
#pragma unroll
        for (int o = 16; o; o >>= 1) s += __shfl_xor_sync(0xffffffffu, s, o);
        if (lane == 0) u[i] = s;
    }
    __syncthreads();
    if (tid < 8) {
        float s = 0.f;
        for (int l = 0; l < SEQL; l++) s += u[l * CHN + tid];
        Usum[tid] = s;
    }
    __syncthreads();
    int ngrp = SEQL / g;
    for (int grp = tid; grp < ngrp * CHN; grp += 256) {
        int gi = grp >> 3, c = grp & 7;
        float s = 0.f;
        for (int l = 0; l < g; l++) s += u[(gi * g + l) * CHN + c];
        float val = (s - ((gi == ngrp - 1) ? Usum[c] : 0.f)) * invg;
        for (int l = 0; l < g; l++) u[(gi * g + l) * CHN + c] = val;
    }
    __syncthreads();
    // sims: u preloaded into registers; 12 LDG.128 + 48 FMA per n
    float4 ur[12];
#pragma unroll
    for (int k = 0; k < 12; k++) ur[k] = *(const float4*)&u[k * 128 + lane * 4];
    int idx = index[b];
    int lo = idx - WIN_HALF, hi = idx + WIN_HALF;
    float bxn = s_bxn, cdot = s_cdot;
    const float* nsq = scr + p * NTRAIN;
    for (int n = wid; n < NTRAIN; n += 8) {
        const float* rp = train + (long)n * FDIM;
        float s = 0.f;
#pragma unroll
        for (int k = 0; k < 12; k++) {
            float4 t = *(const float4*)&rp[k * 128 + lane * 4];
            s = fmaf(t.x, ur[k].x, s); s = fmaf(t.y, ur[k].y, s);
            s = fmaf(t.z, ur[k].z, s); s = fmaf(t.w, ur[k].w, s);
        }
#pragma unroll
        for (int o = 16; o; o >>= 1) s += __shfl_xor_sync(0xffffffffu, s, o);
        if (lane == 0) {
            float v;
            if (n >= lo && n <= hi) v = -1e30f;
            else {
                float an = fmaxf(sqrtf(fmaxf(nsq[n], 0.f)), 1e-12f);
                v = (s + cdot) / (bxn * an);
            }
            sv[n] = v;
        }
    }
    __syncthreads();
    for (int it = 0; it < TOPM; it++) {
        float best = -2e30f;
        int bi = 0x7fffffff;
        for (int n = tid; n < NTRAIN; n += 256) {
            float v = sv[n];
            if (v > best || (v == best && n < bi)) { best = v; bi = n; }
        }
#pragma unroll
        for (int o = 16; o; o >>= 1) {
            float v2 = __shfl_xor_sync(0xffffffffu, best, o);
            int i2 = __shfl_xor_sync(0xffffffffu, bi, o);
            if (v2 > best || (v2 == best && i2 < bi)) { best = v2; bi = i2; }
        }
        if (lane == 0) { wredf[wid] = best; wredi[wid] = bi; }
        __syncthreads();
        if (tid == 0) {
            float bv = wredf[0]; int bw = wredi[0];
            for (int w = 1; w < 8; w++) {
                if (wredf[w] > bv || (wredf[w] == bv && wredi[w] < bw)) { bv = wredf[w]; bw = wredi[w]; }
            }
            if (bw < 0) bw = 0; if (bw >= NTRAIN) bw = NTRAIN - 1;
            g_topidx[pb * TOPM + it] = bw;
            sv[bw] = -1e30f;
        }
        __syncthreads();
    }
}

// ---------------- attention scores: single-pass flash-style online softmax ----
__global__ __launch_bounds__(192) void attn_scores_kernel(const float* __restrict__ x,
                                                          const float* __restrict__ train) {
    __shared__ float kbuf[FDIM];
    __shared__ float sbeta[SEQL];
    __shared__ float sM[64], swqbk[8], swkbq[8];
    __shared__ float sbqbk_s;
    __shared__ int   sidx[TOPM];
    __shared__ float spart_sm[TOPM];
    __shared__ float lastk[8], lastxq[8];
    int tid = threadIdx.x;
    int lane = tid & 31;
    int pb = blockIdx.x;
    int p = pb >> 5, b = pb & 31;
    int g = 4 >> p;
    float invg = 1.0f / (float)g;
    const float* xr = x + (long)b * FDIM;

    if (tid < 64) sM[tid] = g_M[tid];
    else if (tid < 72) swqbk[tid - 64] = g_wqbk[tid - 64];
    else if (tid < 80) swkbq[tid - 72] = g_wkbq[tid - 72];
    else if (tid == 80) sbqbk_s = g_bqbk[0];
    if (tid >= 96 && tid < 96 + TOPM) {
        int w = g_topidx[pb * TOPM + tid - 96];
        sidx[tid - 96] = min(max(w, 0), NTRAIN - 1);
    }
    if (tid >= 128 && tid < 128 + TOPM) spart_sm[tid - 128] = 0.f;
    if (tid >= 160 && tid < 168) {
        int c = tid - 160;
        float s = 0.f;
        for (int j = 0; j < g; j++) s += xr[(SEQL - g + j) * CHN + c];
        lastxq[c] = s * invg;
    }
    __syncthreads();

    const float inv = 0.044194173824159216f;
    float q0 = 0.f, q1 = 0.f, q2 = 0.f, q3 = 0.f, q4 = 0.f, q5 = 0.f, q6 = 0.f, q7 = 0.f;
    float alpha = 0.f;
    {
        int B = (tid / g) * g;
#pragma unroll
        for (int c = 0; c < 8; c++) {
            float s = 0.f;
            for (int j = 0; j < g; j++) s += xr[(B + j) * CHN + c];
            float xv = s * invg - lastxq[c];
            alpha = fmaf(xv, swqbk[c], alpha);
            q0 = fmaf(xv, sM[c * 8 + 0], q0); q1 = fmaf(xv, sM[c * 8 + 1], q1);
            q2 = fmaf(xv, sM[c * 8 + 2], q2); q3 = fmaf(xv, sM[c * 8 + 3], q3);
            q4 = fmaf(xv, sM[c * 8 + 4], q4); q5 = fmaf(xv, sM[c * 8 + 5], q5);
            q6 = fmaf(xv, sM[c * 8 + 6], q6); q7 = fmaf(xv, sM[c * 8 + 7], q7);
        }
    }
    alpha = (alpha + sbqbk_s) * inv;
    q0 *= inv; q1 *= inv; q2 *= inv; q3 *= inv;
    q4 *= inv; q5 *= inv; q6 *= inv; q7 *= inv;

    float S[TOPM];
    float runmax = -3.0e38f, Z = 0.f;
#pragma unroll
    for (int m = 0; m < TOPM; m++) {
        __syncthreads();
        const float* kr = train + (long)sidx[m] * FDIM;
        if (tid < 8) {
            float s = 0.f;
            for (int j = 0; j < g; j++) s += kr[(SEQL - g + j) * CHN + tid];
            lastk[tid] = s * invg;
        }
        __syncthreads();
        for (int f = tid; f < FDIM; f += 192) {
            int l = f >> 3, c = f & 7;
            int B = (l / g) * g;
            float s = 0.f;
            for (int j = 0; j < g; j++) s += kr[(B + j) * CHN + c];
            kbuf[f] = s * invg - lastk[c];
        }
        __syncthreads();
        {
            float bsum = swkbq[0] * kbuf[tid * 8 + 0];
            bsum = fmaf(swkbq[1], kbuf[tid * 8 + 1], bsum);
            bsum = fmaf(swkbq[2], kbuf[tid * 8 + 2], bsum);
            bsum = fmaf(swkbq[3], kbuf[tid * 8 + 3], bsum);
            bsum = fmaf(swkbq[4], kbuf[tid * 8 + 4], bsum);
            bsum = fmaf(swkbq[5], kbuf[tid * 8 + 5], bsum);
            bsum = fmaf(swkbq[6], kbuf[tid * 8 + 6], bsum);
            bsum = fmaf(swkbq[7], kbuf[tid * 8 + 7], bsum);
            sbeta[tid] = bsum * inv;
        }
        __syncthreads();
        float cmax = -3.0e38f, csum = 0.f;
        for (int t = 0; t < SEQL; t++) {
            float v = alpha + sbeta[t];
            v = fmaf(q0, kbuf[t * 8 + 0], v); v = fmaf(q1, kbuf[t * 8 + 1], v);
            v = fmaf(q2, kbuf[t * 8 + 2], v); v = fmaf(q3, kbuf[t * 8 + 3], v);
            v = fmaf(q4, kbuf[t * 8 + 4], v); v = fmaf(q5, kbuf[t * 8 + 5], v);
            v = fmaf(q6, kbuf[t * 8 + 6], v); v = fmaf(q7, kbuf[t * 8 + 7], v);
            if (v > cmax) { csum = csum * fast_exp(cmax - v) + 1.f; cmax = v; }
            else          { csum += fast_exp(v - cmax); }
        }
        float newmax = fmaxf(runmax, cmax);
        float sR = fast_exp(runmax - newmax);
        float sC = fast_exp(cmax - newmax);
        Z = Z * sR + csum * sC;
#pragma unroll
        for (int j = 0; j < TOPM; j++) if (j < m) S[j] *= sR;
        S[m] = csum * sC;
        runmax = newmax;
    }
    float rz = 1.0f / Z;
#pragma unroll
    for (int m = 0; m < TOPM; m++) {
        float wm = S[m] * rz;
#pragma unroll
        for (int o = 16; o; o >>= 1) wm += __shfl_xor_sync(0xffffffffu, wm, o);
        if (lane == 0) atomicAdd(&spart_sm[m], wm);
    }
    __syncthreads();
    if (tid < TOPM) g_spart[pb * TOPM + tid] = spart_sm[tid];
}

// ---------------- output ----------------
__global__ __launch_bounds__(256) void output_kernel(const float* __restrict__ ydata,
                                                     float* __restrict__ out) {
    __shared__ float ssp[TOPM];
    __shared__ float snw[TOPM];
    __shared__ int   sidx[TOPM];
    __shared__ float lastmy[TOPM][8];
    __shared__ float smax, ssum;
    int tid = threadIdx.x;
    int pb = blockIdx.x;
    int p = pb >> 5;
    int g = 4 >> p;
    float invg = 1.0f / (float)g;
    if (tid < TOPM) {
        ssp[tid] = g_spart[pb * TOPM + tid];
        int w = g_topidx[pb * TOPM + tid];
        sidx[tid] = min(max(w, 0), NTRAIN - 1);
    }
    __syncthreads();
    if (tid < TOPM * 8) {
        int m = tid >> 3, c = tid & 7;
        const float* yr = ydata + (long)sidx[m] * YROW;
        float s = 0.f;
        for (int j = 0; j < g; j++) s += yr[(PREDL - g + j) * CHN + c];
        lastmy[m][c] = s * invg;
    }
    if (tid == 224) {
        float mx = ssp[0];
        for (int m = 1; m < TOPM; m++) mx = fmaxf(mx, ssp[m]);
        smax = mx;
    }
    __syncthreads();
    if (tid < TOPM) snw[tid] = expf(ssp[tid] - smax);
    __syncthreads();
    if (tid == 0) {
        float ss = 0.f;
        for (int m = 0; m < TOPM; m++) ss += snw[m];
        ssum = ss;
    }
    __syncthreads();
    if (tid < TOPM) snw[tid] = snw[tid] / ssum;
    __syncthreads();
    for (int i = tid; i < YROW; i += 256) {
        int l = i >> 3, c = i & 7;
        int B = (l / g) * g;
        float acc = 0.f;
#pragma unroll
        for (int m = 0; m < TOPM; m++) {
            const float* yr = ydata + (long)sidx[m] * YROW;
            float s = 0.f;
            for (int j = 0; j < g; j++) s += yr[(B + j) * CHN + c];
            acc = fmaf(snw[m], s * invg - lastmy[m][c], acc);
        }
        out[(long)pb * YROW + i] = acc;
    }
}

// ---------------- launch ----------------
extern "C" void kernel_launch(void* const* d_in, const int* in_sizes, int n_in,
                              void* d_out, int out_size) {
    const float* x     = (const float*)d_in[0];
    const int*   index = (const int*)d_in[1];
    const float* train = (const float*)d_in[2];
    const float* ydata = (const float*)d_in[3];
    const float* W     = (const float*)d_in[4];
    const float* bsim  = (const float*)d_in[5];
    const float* Wq    = (const float*)d_in[6];
    const float* bq    = (const float*)d_in[7];
    const float* Wk    = (const float*)d_in[8];
    const float* bk    = (const float*)d_in[9];
    float* out = (float*)d_out;
    float* scr = out;   // first NP*NTRAIN floats = normsq scratch; overwritten at the end

    prefill_kernel<<<(NP * BSZ * YROW + 255) / 256, 256, 0, STREAM>>>(out);
    clear_scratch_kernel<<<(NP * NTRAIN + 255) / 256, 256, 0, STREAM>>>(scr);
    prep_kernel<<<1, 128, 0, STREAM>>>(Wq, bq, Wk, bk);
    gemm_norm_kernel<<<dim3(79, 12, NP), 256, 0, STREAM>>>(train, W, bsim, scr);
    topk_fused_kernel<<<NP * BSZ, 256, 0, STREAM>>>(x, index, train, W, bsim, scr);
    attn_scores_kernel<<<NP * BSZ, 192, 0, STREAM>>>(x, train);
    output_kernel<<<NP * BSZ, 256, 0, STREAM>>>(ydata, out);
}

// round 17
// speedup vs baseline: 1.0731x; 1.0731x over previous
#include <cuda_runtime.h>
#include <math.h>

#define NTRAIN 10000
#define SEQL   192
#define PREDL  96
#define CHN    8
#define FDIM   1536     // SEQL*CHN
#define YROW   768      // PREDL*CHN
#define TOPM   20
#define BSZ    32
#define NP     3
#define WIN_HALF 287    // (2*(SEQ+PRED)-1 - 1)/2

#define STREAM cudaStreamPerThread

// ---------------- tiny device globals (~16 KB; lazy module load stays in-pool) ----
__device__ int   g_topidx[NP * BSZ * TOPM];
__device__ float g_spart[NP * BSZ * TOPM];
__device__ float g_M[64];
__device__ float g_wqbk[8];
__device__ float g_wkbq[8];
__device__ float g_bqbk[1];

// ---------------- fast exp (FMA-only, scalar-only) ----------------
__device__ __forceinline__ float fast_exp(float x) {
    x = fmaxf(x, -87.0f);
    float t = x * 1.4426950408889634f;
    float z = t + 12582912.0f;
    float n = z - 12582912.0f;
    float f = t - n;
    float p = 0.0013333558146428443f;
    p = fmaf(p, f, 0.009618129107628477f);
    p = fmaf(p, f, 0.05550410866482158f);
    p = fmaf(p, f, 0.2402265069591007f);
    p = fmaf(p, f, 0.6931471805599453f);
    p = fmaf(p, f, 1.0f);
    int ei = (int)n;
    return p * __int_as_float((ei + 127) << 23);
}

__global__ void prefill_kernel(float* __restrict__ out) {
    int i = blockIdx.x * blockDim.x + threadIdx.x;
    if (i < NP * BSZ * YROW) out[i] = 2.0f;
}
__global__ void clear_scratch_kernel(float* __restrict__ scr) {
    int i = blockIdx.x * blockDim.x + threadIdx.x;
    if (i < NP * NTRAIN) scr[i] = 0.0f;
}

// ---------------- prep: M = Wq Wk^T (8x8), Wq.bk, Wk.bq, bq.bk ----------------
__global__ void prep_kernel(const float* __restrict__ Wq, const float* __restrict__ bq,
                            const float* __restrict__ Wk, const float* __restrict__ bk) {
    int t = threadIdx.x;
    if (t < 64) {
        int c = t >> 3, d = t & 7;
        float s = 0.f;
        for (int e = 0; e < 512; e++) s = fmaf(Wq[c * 512 + e], Wk[d * 512 + e], s);
        g_M[t] = s;
    } else if (t < 72) {
        int c = t - 64;
        float s = 0.f;
        for (int e = 0; e < 512; e++) s = fmaf(Wq[c * 512 + e], bk[e], s);
        g_wqbk[c] = s;
    } else if (t < 80) {
        int c = t - 72;
        float s = 0.f;
        for (int e = 0; e < 512; e++) s = fmaf(Wk[c * 512 + e], bq[e], s);
        g_wkbq[c] = s;
    } else if (t == 80) {
        float s = 0.f;
        for (int e = 0; e < 512; e++) s = fmaf(bq[e], bk[e], s);
        g_bqbk[0] = s;
    }
}

// ---------------- grouped-K GEMM, conflict-free B + float4 A fragments ----------------
__global__ __launch_bounds__(256) void gemm_norm_kernel(const float* __restrict__ train,
                                                        const float* __restrict__ W,
                                                        const float* __restrict__ bsim,
                                                        float* __restrict__ scr) {
    int p = blockIdx.z;
    int g = 4 >> p;                      // 4, 2, 1
    int Keff = FDIM / g;                 // 384, 768, 1536
    float invg = 1.0f / (float)g;
    __shared__ float As[16][132];        // row stride 528B (16B-aligned for LDS.128)
    __shared__ float Bs[16][128];
    __shared__ float lastm[128][8];
    __shared__ float red[16][16][8];
    int tid = threadIdx.x;
    int tx = tid & 15, ty = tid >> 4;
    int row0 = blockIdx.x * 128, col0 = blockIdx.y * 128;

    if (tid < 128) {
        int n = row0 + tid;
        float4 s0 = make_float4(0.f, 0.f, 0.f, 0.f);
        float4 s1 = make_float4(0.f, 0.f, 0.f, 0.f);
        if (n < NTRAIN) {
            const float* rp = train + (long)n * FDIM + (SEQL - g) * CHN;
            for (int j = 0; j < g; j++) {
                float4 a = *(const float4*)&rp[j * CHN + 0];
                float4 b = *(const float4*)&rp[j * CHN + 4];
                s0.x += a.x; s0.y += a.y; s0.z += a.z; s0.w += a.w;
                s1.x += b.x; s1.y += b.y; s1.z += b.z; s1.w += b.w;
            }
        }
        lastm[tid][0] = s0.x * invg; lastm[tid][1] = s0.y * invg;
        lastm[tid][2] = s0.z * invg; lastm[tid][3] = s0.w * invg;
        lastm[tid][4] = s1.x * invg; lastm[tid][5] = s1.y * invg;
        lastm[tid][6] = s1.z * invg; lastm[tid][7] = s1.w * invg;
    }
    __syncthreads();

    float acc[8][8];
#pragma unroll
    for (int i = 0; i < 8; i++)
#pragma unroll
        for (int j = 0; j < 8; j++) acc[i][j] = 0.f;

    int lbr = tid >> 5;
    int lbc = (tid & 31) * 4;
    int ar = tid >> 1;
    int ahalf = tid & 1;

    for (int k0 = 0; k0 < Keff; k0 += 16) {
        {
            int n = row0 + ar;
            int gi = (k0 >> 3) + ahalf;
            float4 s0 = make_float4(0.f, 0.f, 0.f, 0.f);
            float4 s1 = make_float4(0.f, 0.f, 0.f, 0.f);
            if (n < NTRAIN) {
                const float* rp = train + (long)n * FDIM + (gi * g) * CHN;
                for (int j = 0; j < g; j++) {
                    float4 a = *(const float4*)&rp[j * CHN + 0];
                    float4 b = *(const float4*)&rp[j * CHN + 4];
                    s0.x += a.x; s0.y += a.y; s0.z += a.z; s0.w += a.w;
                    s1.x += b.x; s1.y += b.y; s1.z += b.z; s1.w += b.w;
                }
            }
            int kk = ahalf * 8;
            As[kk + 0][ar] = s0.x * invg - lastm[ar][0];
            As[kk + 1][ar] = s0.y * invg - lastm[ar][1];
            As[kk + 2][ar] = s0.z * invg - lastm[ar][2];
            As[kk + 3][ar] = s0.w * invg - lastm[ar][3];
            As[kk + 4][ar] = s1.x * invg - lastm[ar][4];
            As[kk + 5][ar] = s1.y * invg - lastm[ar][5];
            As[kk + 6][ar] = s1.z * invg - lastm[ar][6];
            As[kk + 7][ar] = s1.w * invg - lastm[ar][7];
        }
#pragma unroll
        for (int h = 0; h < 2; h++) {
            int r = lbr + h * 8;
            int kp = k0 + r;
            int gi = kp >> 3, c = kp & 7;
            const float* wbase = W + ((long)(gi * g * 8 + c)) * FDIM + col0 + lbc;
            float4 s = make_float4(0.f, 0.f, 0.f, 0.f);
            for (int jj = 0; jj < g; jj++) {
                float4 v = *(const float4*)(wbase + (long)jj * 8 * FDIM);
                s.x += v.x; s.y += v.y; s.z += v.z; s.w += v.w;
            }
            *(float4*)&Bs[r][lbc] = s;
        }
        __syncthreads();
#pragma unroll
        for (int kk = 0; kk < 16; kk++) {
            float a[8], b[8];
            // A fragment: 2x LDS.128 (contiguous, 16B aligned)
            float4 av0 = *(const float4*)&As[kk][ty * 8];
            float4 av1 = *(const float4*)&As[kk][ty * 8 + 4];
            a[0] = av0.x; a[1] = av0.y; a[2] = av0.z; a[3] = av0.w;
            a[4] = av1.x; a[5] = av1.y; a[6] = av1.z; a[7] = av1.w;
            // B fragment: 2x LDS.128 conflict-free split
            float4 bv0 = *(const float4*)&Bs[kk][tx * 4];
            float4 bv1 = *(const float4*)&Bs[kk][64 + tx * 4];
            b[0] = bv0.x; b[1] = bv0.y; b[2] = bv0.z; b[3] = bv0.w;
            b[4] = bv1.x; b[5] = bv1.y; b[6] = bv1.z; b[7] = bv1.w;
#pragma unroll
            for (int i = 0; i < 8; i++)
#pragma unroll
                for (int j = 0; j < 8; j++) acc[i][j] = fmaf(a[i], b[j], acc[i][j]);
        }
        __syncthreads();
    }
    float bb[8];
#pragma unroll
    for (int j = 0; j < 4; j++) bb[j] = bsim[col0 + tx * 4 + j];
#pragma unroll
    for (int j = 0; j < 4; j++) bb[4 + j] = bsim[col0 + 64 + tx * 4 + j];
#pragma unroll
    for (int i = 0; i < 8; i++) {
        float s = 0.f;
#pragma unroll
        for (int j = 0; j < 8; j++) { float v = acc[i][j] + bb[j]; s = fmaf(v, v, s); }
        red[ty][tx][i] = s;
    }
    __syncthreads();
    if (tx < 8) {
        float s = 0.f;
#pragma unroll
        for (int q = 0; q < 16; q++) s += red[ty][q][tx];
        int grow = row0 + ty * 8 + tx;
        if (grow < NTRAIN) atomicAdd(&scr[p * NTRAIN + grow], s);
    }
}

// ---------------- fused bx/u/sims/top-20 per (p,b) — R14-proven scalar version ----
__global__ __launch_bounds__(256) void topk_fused_kernel(const float* __restrict__ x,
                                                         const int* __restrict__ index,
                                                         const float* __restrict__ train,
                                                         const float* __restrict__ W,
                                                         const float* __restrict__ bsim,
                                                         const float* __restrict__ scr) {
    __shared__ float sv[NTRAIN];
    __shared__ float u[FDIM];
    __shared__ float lastx[8];
    __shared__ float Usum[8];
    __shared__ float wredf[8];
    __shared__ int   wredi[8];
    __shared__ float s_bxn, s_cdot;
    int tid = threadIdx.x;
    int lane = tid & 31, wid = tid >> 5;
    int pb = blockIdx.x;
    int p = pb >> 5, b = pb & 31;
    int g = 4 >> p;
    float invg = 1.0f / (float)g;
    const float* xr = x + (long)b * FDIM;
    float* xp = sv + 2048;
    float* bx = sv;

    if (tid < 8) {
        float s = 0.f;
        for (int j = 0; j < g; j++) s += xr[(SEQL - g + j) * CHN + tid];
        lastx[tid] = s * invg;
    }
    __syncthreads();
    for (int f = tid; f < FDIM; f += 256) {
        int l = f >> 3, c = f & 7;
        int B = (l / g) * g;
        float s = 0.f;
        for (int j = 0; j < g; j++) s += xr[(B + j) * CHN + c];
        xp[f] = s * invg - lastx[c];
    }
    __syncthreads();
    float a0 = bsim[tid], a1 = bsim[tid + 256], a2 = bsim[tid + 512];
    float a3 = bsim[tid + 768], a4 = bsim[tid + 1024], a5 = bsim[tid + 1280];
    for (int f = 0; f < FDIM; f++) {
        float xv = xp[f];
        const float* wr = W + (long)f * FDIM + tid;
        a0 = fmaf(xv, wr[0], a0);    a1 = fmaf(xv, wr[256], a1);
        a2 = fmaf(xv, wr[512], a2);  a3 = fmaf(xv, wr[768], a3);
        a4 = fmaf(xv, wr[1024], a4); a5 = fmaf(xv, wr[1280], a5);
    }
    __syncthreads();
    bx[tid] = a0; bx[tid + 256] = a1; bx[tid + 512] = a2;
    bx[tid + 768] = a3; bx[tid + 1024] = a4; bx[tid + 1280] = a5;
    float sq = a0 * a0 + a1 * a1 + a2 * a2 + a3 * a3 + a4 * a4 + a5 * a5;
    float cd = a0 * bsim[tid] + a1 * bsim[tid + 256] + a2 * bsim[tid + 512]
             + a3 * bsim[tid + 768] + a4 * bsim[tid + 1024] + a5 * bsim[tid + 1280];
#pragma unroll
    for (int o = 16; o; o >>= 1) {
        sq += __shfl_xor_sync(0xffffffffu, sq, o);
        cd += __shfl_xor_sync(0xffffffffu, cd, o);
    }
    if (lane == 0) { wredf[wid] = sq; wredi[wid] = __float_as_int(cd); }
    __syncthreads();
    if (tid == 0) {
        float t1 = 0.f, t2 = 0.f;
        for (int w = 0; w < 8; w++) { t1 += wredf[w]; t2 += __int_as_float(wredi[w]); }
        s_bxn = fmaxf(sqrtf(fmaxf(t1, 0.f)), 1e-12f);
        s_cdot = t2;
    }
    __syncthreads();
    for (int i = wid; i < FDIM; i += 8) {
        const float* wr = W + (long)i * FDIM;
        float s = 0.f;
        for (int f = lane; f < FDIM; f += 32) s = fmaf(wr[f], bx[f], s);
#pragma unroll
        for (int o = 16; o; o >>= 1) s += __shfl_xor_sync(0xffffffffu, s, o);
        if (lane == 0) u[i] = s;
    }
    __syncthreads();
    if (tid < 8) {
        float s = 0.f;
        for (int l = 0; l < SEQL; l++) s += u[l * CHN + tid];
        Usum[tid] = s;
    }
    __syncthreads();
    int ngrp = SEQL / g;
    for (int grp = tid; grp < ngrp * CHN; grp += 256) {
        int gi = grp >> 3, c = grp & 7;
        float s = 0.f;
        for (int l = 0; l < g; l++) s += u[(gi * g + l) * CHN + c];
        float val = (s - ((gi == ngrp - 1) ? Usum[c] : 0.f)) * invg;
        for (int l = 0; l < g; l++) u[(gi * g + l) * CHN + c] = val;
    }
    __syncthreads();
    int idx = index[b];
    int lo = idx - WIN_HALF, hi = idx + WIN_HALF;
    float bxn = s_bxn, cdot = s_cdot;
    const float* nsq = scr + p * NTRAIN;
    for (int n = wid; n < NTRAIN; n += 8) {
        const float* rp = train + (long)n * FDIM;
        float s = 0.f;
        for (int f = lane; f < FDIM; f += 32) s = fmaf(rp[f], u[f], s);
#pragma unroll
        for (int o = 16; o; o >>= 1) s += __shfl_xor_sync(0xffffffffu, s, o);
        if (lane == 0) {
            float v;
            if (n >= lo && n <= hi) v = -1e30f;
            else {
                float an = fmaxf(sqrtf(fmaxf(nsq[n], 0.f)), 1e-12f);
                v = (s + cdot) / (bxn * an);
            }
            sv[n] = v;
        }
    }
    __syncthreads();
    for (int it = 0; it < TOPM; it++) {
        float best = -2e30f;
        int bi = 0x7fffffff;
        for (int n = tid; n < NTRAIN; n += 256) {
            float v = sv[n];
            if (v > best || (v == best && n < bi)) { best = v; bi = n; }
        }
#pragma unroll
        for (int o = 16; o; o >>= 1) {
            float v2 = __shfl_xor_sync(0xffffffffu, best, o);
            int i2 = __shfl_xor_sync(0xffffffffu, bi, o);
            if (v2 > best || (v2 == best && i2 < bi)) { best = v2; bi = i2; }
        }
        if (lane == 0) { wredf[wid] = best; wredi[wid] = bi; }
        __syncthreads();
        if (tid == 0) {
            float bv = wredf[0]; int bw = wredi[0];
            for (int w = 1; w < 8; w++) {
                if (wredf[w] > bv || (wredf[w] == bv && wredi[w] < bw)) { bv = wredf[w]; bw = wredi[w]; }
            }
            if (bw < 0) bw = 0; if (bw >= NTRAIN) bw = NTRAIN - 1;
            g_topidx[pb * TOPM + it] = bw;
            sv[bw] = -1e30f;
        }
        __syncthreads();
    }
}

// ---------------- attention scores: single-pass flash-style online softmax ----
__global__ __launch_bounds__(192) void attn_scores_kernel(const float* __restrict__ x,
                                                          const float* __restrict__ train) {
    __shared__ float kbuf[FDIM];
    __shared__ float sbeta[SEQL];
    __shared__ float sM[64], swqbk[8], swkbq[8];
    __shared__ float sbqbk_s;
    __shared__ int   sidx[TOPM];
    __shared__ float spart_sm[TOPM];
    __shared__ float lastk[8], lastxq[8];
    int tid = threadIdx.x;
    int lane = tid & 31;
    int pb = blockIdx.x;
    int p = pb >> 5, b = pb & 31;
    int g = 4 >> p;
    float invg = 1.0f / (float)g;
    const float* xr = x + (long)b * FDIM;

    if (tid < 64) sM[tid] = g_M[tid];
    else if (tid < 72) swqbk[tid - 64] = g_wqbk[tid - 64];
    else if (tid < 80) swkbq[tid - 72] = g_wkbq[tid - 72];
    else if (tid == 80) sbqbk_s = g_bqbk[0];
    if (tid >= 96 && tid < 96 + TOPM) {
        int w = g_topidx[pb * TOPM + tid - 96];
        sidx[tid - 96] = min(max(w, 0), NTRAIN - 1);
    }
    if (tid >= 128 && tid < 128 + TOPM) spart_sm[tid - 128] = 0.f;
    if (tid >= 160 && tid < 168) {
        int c = tid - 160;
        float s = 0.f;
        for (int j = 0; j < g; j++) s += xr[(SEQL - g + j) * CHN + c];
        lastxq[c] = s * invg;
    }
    __syncthreads();

    const float inv = 0.044194173824159216f;
    float q0 = 0.f, q1 = 0.f, q2 = 0.f, q3 = 0.f, q4 = 0.f, q5 = 0.f, q6 = 0.f, q7 = 0.f;
    float alpha = 0.f;
    {
        int B = (tid / g) * g;
#pragma unroll
        for (int c = 0; c < 8; c++) {
            float s = 0.f;
            for (int j = 0; j < g; j++) s += xr[(B + j) * CHN + c];
            float xv = s * invg - lastxq[c];
            alpha = fmaf(xv, swqbk[c], alpha);
            q0 = fmaf(xv, sM[c * 8 + 0], q0); q1 = fmaf(xv, sM[c * 8 + 1], q1);
            q2 = fmaf(xv, sM[c * 8 + 2], q2); q3 = fmaf(xv, sM[c * 8 + 3], q3);
            q4 = fmaf(xv, sM[c * 8 + 4], q4); q5 = fmaf(xv, sM[c * 8 + 5], q5);
            q6 = fmaf(xv, sM[c * 8 + 6], q6); q7 = fmaf(xv, sM[c * 8 + 7], q7);
        }
    }
    alpha = (alpha + sbqbk_s) * inv;
    q0 *= inv; q1 *= inv; q2 *= inv; q3 *= inv;
    q4 *= inv; q5 *= inv; q6 *= inv; q7 *= inv;

    float S[TOPM];
    float runmax = -3.0e38f, Z = 0.f;
#pragma unroll
    for (int m = 0; m < TOPM; m++) {
        __syncthreads();
        const float* kr = train + (long)sidx[m] * FDIM;
        if (tid < 8) {
            float s = 0.f;
            for (int j = 0; j < g; j++) s += kr[(SEQL - g + j) * CHN + tid];
            lastk[tid] = s * invg;
        }
        __syncthreads();
        for (int f = tid; f < FDIM; f += 192) {
            int l = f >> 3, c = f & 7;
            int B = (l / g) * g;
            float s = 0.f;
            for (int j = 0; j < g; j++) s += kr[(B + j) * CHN + c];
            kbuf[f] = s * invg - lastk[c];
        }
        __syncthreads();
        {
            float bsum = swkbq[0] * kbuf[tid * 8 + 0];
            bsum = fmaf(swkbq[1], kbuf[tid * 8 + 1], bsum);
            bsum = fmaf(swkbq[2], kbuf[tid * 8 + 2], bsum);
            bsum = fmaf(swkbq[3], kbuf[tid * 8 + 3], bsum);
            bsum = fmaf(swkbq[4], kbuf[tid * 8 + 4], bsum);
            bsum = fmaf(swkbq[5], kbuf[tid * 8 + 5], bsum);
            bsum = fmaf(swkbq[6], kbuf[tid * 8 + 6], bsum);
            bsum = fmaf(swkbq[7], kbuf[tid * 8 + 7], bsum);
            sbeta[tid] = bsum * inv;
        }
        __syncthreads();
        float cmax = -3.0e38f, csum = 0.f;
        for (int t = 0; t < SEQL; t++) {
            float v = alpha + sbeta[t];
            v = fmaf(q0, kbuf[t * 8 + 0], v); v = fmaf(q1, kbuf[t * 8 + 1], v);
            v = fmaf(q2, kbuf[t * 8 + 2], v); v = fmaf(q3, kbuf[t * 8 + 3], v);
            v = fmaf(q4, kbuf[t * 8 + 4], v); v = fmaf(q5, kbuf[t * 8 + 5], v);
            v = fmaf(q6, kbuf[t * 8 + 6], v); v = fmaf(q7, kbuf[t * 8 + 7], v);
            if (v > cmax) { csum = csum * fast_exp(cmax - v) + 1.f; cmax = v; }
            else          { csum += fast_exp(v - cmax); }
        }
        float newmax = fmaxf(runmax, cmax);
        float sR = fast_exp(runmax - newmax);
        float sC = fast_exp(cmax - newmax);
        Z = Z * sR + csum * sC;
#pragma unroll
        for (int j = 0; j < TOPM; j++) if (j < m) S[j] *= sR;
        S[m] = csum * sC;
        runmax = newmax;
    }
    float rz = 1.0f / Z;
#pragma unroll
    for (int m = 0; m < TOPM; m++) {
        float wm = S[m] * rz;
#pragma unroll
        for (int o = 16; o; o >>= 1) wm += __shfl_xor_sync(0xffffffffu, wm, o);
        if (lane == 0) atomicAdd(&spart_sm[m], wm);
    }
    __syncthreads();
    if (tid < TOPM) g_spart[pb * TOPM + tid] = spart_sm[tid];
}

// ---------------- output ----------------
__global__ __launch_bounds__(256) void output_kernel(const float* __restrict__ ydata,
                                                     float* __restrict__ out) {
    __shared__ float ssp[TOPM];
    __shared__ float snw[TOPM];
    __shared__ int   sidx[TOPM];
    __shared__ float lastmy[TOPM][8];
    __shared__ float smax, ssum;
    int tid = threadIdx.x;
    int pb = blockIdx.x;
    int p = pb >> 5;
    int g = 4 >> p;
    float invg = 1.0f / (float)g;
    if (tid < TOPM) {
        ssp[tid] = g_spart[pb * TOPM + tid];
        int w = g_topidx[pb * TOPM + tid];
        sidx[tid] = min(max(w, 0), NTRAIN - 1);
    }
    __syncthreads();
    if (tid < TOPM * 8) {
        int m = tid >> 3, c = tid & 7;
        const float* yr = ydata + (long)sidx[m] * YROW;
        float s = 0.f;
        for (int j = 0; j < g; j++) s += yr[(PREDL - g + j) * CHN + c];
        lastmy[m][c] = s * invg;
    }
    if (tid == 224) {
        float mx = ssp[0];
        for (int m = 1; m < TOPM; m++) mx = fmaxf(mx, ssp[m]);
        smax = mx;
    }
    __syncthreads();
    if (tid < TOPM) snw[tid] = expf(ssp[tid] - smax);
    __syncthreads();
    if (tid == 0) {
        float ss = 0.f;
        for (int m = 0; m < TOPM; m++) ss += snw[m];
        ssum = ss;
    }
    __syncthreads();
    if (tid < TOPM) snw[tid] = snw[tid] / ssum;
    __syncthreads();
    for (int i = tid; i < YROW; i += 256) {
        int l = i >> 3, c = i & 7;
        int B = (l / g) * g;
        float acc = 0.f;
#pragma unroll
        for (int m = 0; m < TOPM; m++) {
            const float* yr = ydata + (long)sidx[m] * YROW;
            float s = 0.f;
            for (int j = 0; j < g; j++) s += yr[(B + j) * CHN + c];
            acc = fmaf(snw[m], s * invg - lastmy[m][c], acc);
        }
        out[(long)pb * YROW + i] = acc;
    }
}

// ---------------- launch ----------------
extern "C" void kernel_launch(void* const* d_in, const int* in_sizes, int n_in,
                              void* d_out, int out_size) {
    const float* x     = (const float*)d_in[0];
    const int*   index = (const int*)d_in[1];
    const float* train = (const float*)d_in[2];
    const float* ydata = (const float*)d_in[3];
    const float* W     = (const float*)d_in[4];
    const float* bsim  = (const float*)d_in[5];
    const float* Wq    = (const float*)d_in[6];
    const float* bq    = (const float*)d_in[7];
    const float* Wk    = (const float*)d_in[8];
    const float* bk    = (const float*)d_in[9];
    float* out = (float*)d_out;
    float* scr = out;   // first NP*NTRAIN floats = normsq scratch; overwritten at the end

    prefill_kernel<<<(NP * BSZ * YROW + 255) / 256, 256, 0, STREAM>>>(out);
    clear_scratch_kernel<<<(NP * NTRAIN + 255) / 256, 256, 0, STREAM>>>(scr);
    prep_kernel<<<1, 128, 0, STREAM>>>(Wq, bq, Wk, bk);
    gemm_norm_kernel<<<dim3(79, 12, NP), 256, 0, STREAM>>>(train, W, bsim, scr);
    topk_fused_kernel<<<NP * BSZ, 256, 0, STREAM>>>(x, index, train, W, bsim, scr);
    attn_scores_kernel<<<NP * BSZ, 192, 0, STREAM>>>(x, train);
    output_kernel<<<NP * BSZ, 256, 0, STREAM>>>(ydata, out);
}